// round 1
// baseline (speedup 1.0000x reference)
#include <cuda_runtime.h>
#include <math.h>

#define N_PTS 80000
#define H_NB  32
#define K_KP  15
#define CIN   128
#define COUT  256
#define D2    64
#define INV_INFL 2.5f       /* 1 / 0.4 */
#define EPS   1e-5f
#define SLOPE 0.2f

// ---------------- scratch (device globals: no allocs allowed) ----------------
__device__ float g_y1 [N_PTS * D2];          // feats @ W1 (pre-BN)
__device__ float g_x1 [N_PTS * D2];          // act(BN1(y1))
__device__ float g_ysc[N_PTS * COUT];        // feats @ Wsc (pre-BN)
__device__ float g_y2 [N_PTS * COUT];        // x @ W2 (pre-BN)
__device__ float g_fk [N_PTS * K_KP * D2];   // [N, 15, 64] kernel-point features
// BN stats/affine, channel layout: [0,64)=BN1, [64,320)=BN2, [320,576)=BNsc
__device__ float g_sum[576];
__device__ float g_sqs[576];
__device__ float g_scale[576];
__device__ float g_bias[576];

__device__ __forceinline__ float lrelu(float v) { return v > 0.f ? v : SLOPE * v; }

// ---------------- zero stats (graph replays must re-zero) ----------------
__global__ void k_zero() {
    int t = threadIdx.x;
    if (t < 576) { g_sum[t] = 0.f; g_sqs[t] = 0.f; }
}

// ---------------- fused GEMM: y1 = feats@W1 (64 cols), ysc = feats@Wsc (256 cols) ----
// grid 625 blocks x 256 thr, 128-row tiles. smem: A[128][132] + W[128][68]
__global__ __launch_bounds__(256) void k_gemm1sc(const float* __restrict__ feats,
                                                 const float* __restrict__ W1,
                                                 const float* __restrict__ Wsc) {
    extern __shared__ float sm[];
    float* As = sm;              // 128 x 132
    float* Ws = sm + 128 * 132;  // 128 x 68
    int t = threadIdx.x;
    int row0 = blockIdx.x * 128;

    for (int i = t; i < 128 * 32; i += 256) {
        int r = i >> 5, q = i & 31;
        *(float4*)&As[r * 132 + q * 4] =
            *(const float4*)&feats[(size_t)(row0 + r) * CIN + q * 4];
    }
    int tr = t >> 4, tc = t & 15;
    int r0 = tr * 8, c0 = tc * 4;

    for (int ct = 0; ct < 5; ++ct) {
        __syncthreads();
        if (ct == 0) {
            for (int i = t; i < 128 * 16; i += 256) {
                int r = i >> 4, q = i & 15;
                *(float4*)&Ws[r * 68 + q * 4] = *(const float4*)&W1[r * 64 + q * 4];
            }
        } else {
            int cb = (ct - 1) * 64;
            for (int i = t; i < 128 * 16; i += 256) {
                int r = i >> 4, q = i & 15;
                *(float4*)&Ws[r * 68 + q * 4] = *(const float4*)&Wsc[r * 256 + cb + q * 4];
            }
        }
        __syncthreads();

        float acc[8][4];
        #pragma unroll
        for (int i = 0; i < 8; ++i)
            #pragma unroll
            for (int j = 0; j < 4; ++j) acc[i][j] = 0.f;

        #pragma unroll 4
        for (int k = 0; k < 128; ++k) {
            float4 b = *(float4*)&Ws[k * 68 + c0];
            #pragma unroll
            for (int i = 0; i < 8; ++i) {
                float a = As[(r0 + i) * 132 + k];
                acc[i][0] += a * b.x; acc[i][1] += a * b.y;
                acc[i][2] += a * b.z; acc[i][3] += a * b.w;
            }
        }
        if (ct == 0) {
            #pragma unroll
            for (int i = 0; i < 8; ++i) {
                float4 v = make_float4(acc[i][0], acc[i][1], acc[i][2], acc[i][3]);
                *(float4*)&g_y1[(size_t)(row0 + r0 + i) * 64 + c0] = v;
            }
        } else {
            int cb = (ct - 1) * 64;
            #pragma unroll
            for (int i = 0; i < 8; ++i) {
                float4 v = make_float4(acc[i][0], acc[i][1], acc[i][2], acc[i][3]);
                *(float4*)&g_ysc[(size_t)(row0 + r0 + i) * 256 + cb + c0] = v;
            }
        }
    }
}

// ---------------- column sums / sumsq over [N, C] ----------------
// which: 0=g_y1(C=64), 1=g_y2(C=256), 2=g_ysc(C=256)
__global__ void k_stats(int which, int C, int off) {
    const float* y = (which == 0) ? g_y1 : (which == 1) ? g_y2 : g_ysc;
    int t = threadIdx.x;
    int col = t % C;
    int rpb = 256 / C;
    int r = blockIdx.x * rpb + t / C;
    int stride = gridDim.x * rpb;
    float s = 0.f, s2 = 0.f;
    for (; r < N_PTS; r += stride) {
        float v = y[(size_t)r * C + col];
        s += v; s2 += v * v;
    }
    atomicAdd(&g_sum[off + col], s);
    atomicAdd(&g_sqs[off + col], s2);
}

__global__ void k_finalize(const float* __restrict__ g, const float* __restrict__ b,
                           int C, int off) {
    int c = blockIdx.x * blockDim.x + threadIdx.x;
    if (c >= C) return;
    float m  = g_sum[off + c] * (1.f / N_PTS);
    float v  = g_sqs[off + c] * (1.f / N_PTS) - m * m;
    float sc = g[c] * rsqrtf(v + EPS);
    g_scale[off + c] = sc;
    g_bias[off + c]  = b[c] - m * sc;
}

// ---------------- x1 = leakyrelu(BN1(y1)) ----------------
__global__ void k_bnact1() {
    int i = blockIdx.x * blockDim.x + threadIdx.x;   // float4 index
    if (i >= N_PTS * 16) return;
    int c = (i * 4) & 63;
    float4 v  = *(float4*)&g_y1[(size_t)i * 4];
    float4 s  = *(float4*)&g_scale[c];
    float4 bb = *(float4*)&g_bias[c];
    float4 o;
    o.x = lrelu(v.x * s.x + bb.x);
    o.y = lrelu(v.y * s.y + bb.y);
    o.z = lrelu(v.z * s.z + bb.z);
    o.w = lrelu(v.w * s.w + bb.w);
    *(float4*)&g_x1[(size_t)i * 4] = o;
}

// ---------------- KPConv gather + influence + fk accumulation ----------------
// one block per point, 128 threads
__global__ __launch_bounds__(128) void k_kpconv(const float* __restrict__ xyz,
                                                const int* __restrict__ nidx,
                                                const float* __restrict__ kp) {
    __shared__ float nxs[32][68];
    __shared__ float ws [32][16];
    __shared__ float rel[32][3];
    __shared__ int   idxs[32];
    int n = blockIdx.x, t = threadIdx.x;

    if (t < 32) idxs[t] = nidx[(size_t)n * 32 + t];
    __syncthreads();

    {   // gather neighbor features (hits L2: x1 is 20.5 MB)
        int h = t >> 2, q = t & 3;
        const float* src = g_x1 + (size_t)idxs[h] * 64 + q * 16;
        #pragma unroll
        for (int j = 0; j < 4; ++j)
            *(float4*)&nxs[h][q * 16 + j * 4] = *(const float4*)&src[j * 4];
    }
    if (t < 32) {
        int id = idxs[t];
        rel[t][0] = xyz[(size_t)id * 3 + 0] - xyz[(size_t)n * 3 + 0];
        rel[t][1] = xyz[(size_t)id * 3 + 1] - xyz[(size_t)n * 3 + 1];
        rel[t][2] = xyz[(size_t)id * 3 + 2] - xyz[(size_t)n * 3 + 2];
    }
    __syncthreads();

    for (int i = t; i < 32 * 16; i += 128) {
        int hh = i >> 4, k = i & 15;
        float wv = 0.f;
        if (k < 15) {
            float dx = rel[hh][0] - kp[k * 3 + 0];
            float dy = rel[hh][1] - kp[k * 3 + 1];
            float dz = rel[hh][2] - kp[k * 3 + 2];
            wv = fmaxf(1.f - sqrtf(dx * dx + dy * dy + dz * dz) * INV_INFL, 0.f);
        }
        ws[hh][k] = wv;
    }
    __syncthreads();

    int d = t & 63, half = t >> 6;
    int k0 = half * 8;
    float acc[8];
    #pragma unroll
    for (int j = 0; j < 8; ++j) acc[j] = 0.f;

    #pragma unroll 4
    for (int hh = 0; hh < 32; ++hh) {
        float nv = nxs[hh][d];
        float4 w0 = *(float4*)&ws[hh][k0];
        float4 w1 = *(float4*)&ws[hh][k0 + 4];
        acc[0] += w0.x * nv; acc[1] += w0.y * nv;
        acc[2] += w0.z * nv; acc[3] += w0.w * nv;
        acc[4] += w1.x * nv; acc[5] += w1.y * nv;
        acc[6] += w1.z * nv; acc[7] += w1.w * nv;
    }
    float* dst = g_fk + (size_t)n * 960 + d;
    #pragma unroll
    for (int j = 0; j < 8; ++j) {
        int k = k0 + j;
        if (k < 15) dst[k * 64] = acc[j];
    }
}

// ---------------- fused X = FK@Wflat[960,64]  then  y2 = X@W2[64,256] ----------------
// grid 625 x 256 thr, 128-row tiles. dynamic smem: FK[128][68] + Wf[64][68] + X[128][68]
__global__ __launch_bounds__(256) void k_gemm2(const float* __restrict__ kpw,
                                               const float* __restrict__ W2) {
    extern __shared__ float sm[];
    float* FKs = sm;                       // 128 x 68
    float* Wfs = sm + 128 * 68;            // 64 x 68
    float* Xs  = sm + 128 * 68 + 64 * 68;  // 128 x 68
    float* W2s = sm;                       // alias FKs/Wfs region in phase B (64 x 132)

    int t = threadIdx.x;
    int row0 = blockIdx.x * 128;
    int tr = t >> 4, tc = t & 15;
    int r0 = tr * 8, c0 = tc * 4;

    float xacc[8][4];
    #pragma unroll
    for (int i = 0; i < 8; ++i)
        #pragma unroll
        for (int j = 0; j < 4; ++j) xacc[i][j] = 0.f;

    for (int k = 0; k < 15; ++k) {
        __syncthreads();
        for (int i = t; i < 128 * 16; i += 256) {
            int r = i >> 4, q = i & 15;
            *(float4*)&FKs[r * 68 + q * 4] =
                *(const float4*)&g_fk[(size_t)(row0 + r) * 960 + k * 64 + q * 4];
        }
        for (int i = t; i < 64 * 16; i += 256) {
            int r = i >> 4, q = i & 15;
            *(float4*)&Wfs[r * 68 + q * 4] =
                *(const float4*)&kpw[k * 4096 + r * 64 + q * 4];
        }
        __syncthreads();
        #pragma unroll 4
        for (int kk = 0; kk < 64; ++kk) {
            float4 b = *(float4*)&Wfs[kk * 68 + c0];
            #pragma unroll
            for (int i = 0; i < 8; ++i) {
                float a = FKs[(r0 + i) * 68 + kk];
                xacc[i][0] += a * b.x; xacc[i][1] += a * b.y;
                xacc[i][2] += a * b.z; xacc[i][3] += a * b.w;
            }
        }
    }
    __syncthreads();
    #pragma unroll
    for (int i = 0; i < 8; ++i) {
        float4 v = make_float4(xacc[i][0], xacc[i][1], xacc[i][2], xacc[i][3]);
        *(float4*)&Xs[(r0 + i) * 68 + c0] = v;
    }

    // phase B: y2 tile = Xs[128,64] @ W2[64, 256] in two 128-col halves
    int c2 = tc * 8;
    for (int ch = 0; ch < 2; ++ch) {
        __syncthreads();   // Xs written (ch==0) / previous W2s reads done (ch==1)
        for (int i = t; i < 64 * 32; i += 256) {
            int r = i >> 5, q = i & 31;
            *(float4*)&W2s[r * 132 + q * 4] =
                *(const float4*)&W2[r * 256 + ch * 128 + q * 4];
        }
        __syncthreads();

        float acc2[8][8];
        #pragma unroll
        for (int i = 0; i < 8; ++i)
            #pragma unroll
            for (int j = 0; j < 8; ++j) acc2[i][j] = 0.f;

        #pragma unroll 2
        for (int kk = 0; kk < 64; ++kk) {
            float4 b0 = *(float4*)&W2s[kk * 132 + c2];
            float4 b1 = *(float4*)&W2s[kk * 132 + c2 + 4];
            #pragma unroll
            for (int i = 0; i < 8; ++i) {
                float a = Xs[(r0 + i) * 68 + kk];
                acc2[i][0] += a * b0.x; acc2[i][1] += a * b0.y;
                acc2[i][2] += a * b0.z; acc2[i][3] += a * b0.w;
                acc2[i][4] += a * b1.x; acc2[i][5] += a * b1.y;
                acc2[i][6] += a * b1.z; acc2[i][7] += a * b1.w;
            }
        }
        #pragma unroll
        for (int i = 0; i < 8; ++i) {
            size_t base = (size_t)(row0 + r0 + i) * 256 + ch * 128 + c2;
            *(float4*)&g_y2[base]     = make_float4(acc2[i][0], acc2[i][1], acc2[i][2], acc2[i][3]);
            *(float4*)&g_y2[base + 4] = make_float4(acc2[i][4], acc2[i][5], acc2[i][6], acc2[i][7]);
        }
    }
}

// ---------------- out = leakyrelu(BN2(y2)) + BNsc(ysc) ----------------
__global__ void k_final(float* __restrict__ out) {
    int i = blockIdx.x * blockDim.x + threadIdx.x;   // float4 index
    if (i >= N_PTS * 64) return;
    int c = (i & 63) * 4;
    float4 y   = *(float4*)&g_y2 [(size_t)i * 4];
    float4 s2  = *(float4*)&g_scale[64 + c];
    float4 b2  = *(float4*)&g_bias [64 + c];
    float4 ys  = *(float4*)&g_ysc[(size_t)i * 4];
    float4 ssc = *(float4*)&g_scale[320 + c];
    float4 bsc = *(float4*)&g_bias [320 + c];
    float4 o;
    o.x = lrelu(y.x * s2.x + b2.x) + ys.x * ssc.x + bsc.x;
    o.y = lrelu(y.y * s2.y + b2.y) + ys.y * ssc.y + bsc.y;
    o.z = lrelu(y.z * s2.z + b2.z) + ys.z * ssc.z + bsc.z;
    o.w = lrelu(y.w * s2.w + b2.w) + ys.w * ssc.w + bsc.w;
    *(float4*)&out[(size_t)i * 4] = o;
}

// ---------------- launch ----------------
extern "C" void kernel_launch(void* const* d_in, const int* in_sizes, int n_in,
                              void* d_out, int out_size) {
    const float* feats = (const float*)d_in[0];
    const float* xyz   = (const float*)d_in[1];
    const int*   nidx  = (const int*)  d_in[3];
    const float* W1    = (const float*)d_in[4];
    const float* g1    = (const float*)d_in[5];
    const float* b1    = (const float*)d_in[6];
    const float* kp    = (const float*)d_in[7];
    const float* kpw   = (const float*)d_in[8];
    const float* W2    = (const float*)d_in[9];
    const float* g2    = (const float*)d_in[10];
    const float* b2    = (const float*)d_in[11];
    const float* Wsc   = (const float*)d_in[12];
    const float* gsc   = (const float*)d_in[13];
    const float* bsc   = (const float*)d_in[14];
    float* out = (float*)d_out;

    const int SM1 = (128 * 132 + 128 * 68) * 4;            // 102400 B
    const int SM2 = (128 * 68 * 2 + 64 * 68) * 4;          // 87040 B
    cudaFuncSetAttribute(k_gemm1sc, cudaFuncAttributeMaxDynamicSharedMemorySize, SM1);
    cudaFuncSetAttribute(k_gemm2,   cudaFuncAttributeMaxDynamicSharedMemorySize, SM2);

    k_zero<<<1, 576>>>();
    k_gemm1sc<<<625, 256, SM1>>>(feats, W1, Wsc);
    k_stats<<<256, 256>>>(0, 64, 0);       // BN1 stats
    k_stats<<<256, 256>>>(2, 256, 320);    // BNsc stats
    k_finalize<<<1, 64>>>(g1, b1, 64, 0);
    k_finalize<<<1, 256>>>(gsc, bsc, 256, 320);
    k_bnact1<<<(N_PTS * 16 + 255) / 256, 256>>>();
    k_kpconv<<<N_PTS, 128>>>(xyz, nidx, kp);
    k_gemm2<<<625, 256, SM2>>>(kpw, W2);
    k_stats<<<256, 256>>>(1, 256, 64);     // BN2 stats
    k_finalize<<<1, 256>>>(g2, b2, 256, 64);
    k_final<<<(N_PTS * 64 + 255) / 256, 256>>>(out);
}

// round 2
// speedup vs baseline: 1.1024x; 1.1024x over previous
#include <cuda_runtime.h>
#include <math.h>

#define N_PTS 80000
#define H_NB  32
#define K_KP  15
#define CIN   128
#define COUT  256
#define D2    64
#define INV_INFL 2.5f       /* 1 / 0.4 */
#define EPS   1e-5f
#define SLOPE 0.2f

// ---------------- scratch (device globals: no allocs allowed) ----------------
__device__ float g_y1 [N_PTS * D2];          // feats @ W1 (pre-BN)
__device__ float g_x1 [N_PTS * D2];          // act(BN1(y1))
__device__ float g_ysc[N_PTS * COUT];        // feats @ Wsc (pre-BN)
__device__ float g_y2 [N_PTS * COUT];        // x @ W2 (pre-BN)
__device__ float g_fk [N_PTS * K_KP * D2];   // [N, 15, 64] kernel-point features
// BN stats/affine, channel layout: [0,64)=BN1, [64,320)=BN2, [320,576)=BNsc
__device__ float g_sum[576];
__device__ float g_sqs[576];
__device__ float g_scale[576];
__device__ float g_bias[576];

__device__ __forceinline__ float lrelu(float v) { return v > 0.f ? v : SLOPE * v; }

// ---------------- zero stats (graph replays must re-zero) ----------------
__global__ void k_zero() {
    int t = threadIdx.x;
    if (t < 576) { g_sum[t] = 0.f; g_sqs[t] = 0.f; }
}

// ---------------- fused GEMM: y1 = feats@W1 (64 cols), ysc = feats@Wsc (256 cols) ----
// grid 625 blocks x 256 thr, 128-row tiles. smem: A[128][132] + W[128][68] + rbuf 2x8x64
// BN1 + BNsc column stats fused into epilogue (shfl + warp-buffer + 1 atomic/col/block)
__global__ __launch_bounds__(256) void k_gemm1sc(const float* __restrict__ feats,
                                                 const float* __restrict__ W1,
                                                 const float* __restrict__ Wsc) {
    extern __shared__ float sm[];
    float* As    = sm;                    // 128 x 132
    float* Ws    = sm + 128 * 132;        // 128 x 68
    float* rbufS = sm + 128 * 132 + 128 * 68;   // 8 x 64
    float* rbufQ = rbufS + 8 * 64;              // 8 x 64
    int t = threadIdx.x;
    int row0 = blockIdx.x * 128;

    for (int i = t; i < 128 * 32; i += 256) {
        int r = i >> 5, q = i & 31;
        *(float4*)&As[r * 132 + q * 4] =
            *(const float4*)&feats[(size_t)(row0 + r) * CIN + q * 4];
    }
    int tr = t >> 4, tc = t & 15;
    int r0 = tr * 8, c0 = tc * 4;
    int lane = t & 31, wrp = t >> 5;

    for (int ct = 0; ct < 5; ++ct) {
        __syncthreads();
        if (ct == 0) {
            for (int i = t; i < 128 * 16; i += 256) {
                int r = i >> 4, q = i & 15;
                *(float4*)&Ws[r * 68 + q * 4] = *(const float4*)&W1[r * 64 + q * 4];
            }
        } else {
            int cb = (ct - 1) * 64;
            for (int i = t; i < 128 * 16; i += 256) {
                int r = i >> 4, q = i & 15;
                *(float4*)&Ws[r * 68 + q * 4] = *(const float4*)&Wsc[r * 256 + cb + q * 4];
            }
        }
        __syncthreads();

        float acc[8][4];
        #pragma unroll
        for (int i = 0; i < 8; ++i)
            #pragma unroll
            for (int j = 0; j < 4; ++j) acc[i][j] = 0.f;

        #pragma unroll 4
        for (int k = 0; k < 128; ++k) {
            float4 b = *(float4*)&Ws[k * 68 + c0];
            #pragma unroll
            for (int i = 0; i < 8; ++i) {
                float a = As[(r0 + i) * 132 + k];
                acc[i][0] += a * b.x; acc[i][1] += a * b.y;
                acc[i][2] += a * b.z; acc[i][3] += a * b.w;
            }
        }
        if (ct == 0) {
            #pragma unroll
            for (int i = 0; i < 8; ++i) {
                float4 v = make_float4(acc[i][0], acc[i][1], acc[i][2], acc[i][3]);
                *(float4*)&g_y1[(size_t)(row0 + r0 + i) * 64 + c0] = v;
            }
        } else {
            int cb = (ct - 1) * 64;
            #pragma unroll
            for (int i = 0; i < 8; ++i) {
                float4 v = make_float4(acc[i][0], acc[i][1], acc[i][2], acc[i][3]);
                *(float4*)&g_ysc[(size_t)(row0 + r0 + i) * 256 + cb + c0] = v;
            }
        }
        // ---- fused column stats ----
        float ps[4], pq[4];
        #pragma unroll
        for (int j = 0; j < 4; ++j) {
            float s = 0.f, q2 = 0.f;
            #pragma unroll
            for (int i = 0; i < 8; ++i) { float v = acc[i][j]; s += v; q2 += v * v; }
            ps[j] = s; pq[j] = q2;
        }
        #pragma unroll
        for (int j = 0; j < 4; ++j) {
            ps[j] += __shfl_xor_sync(0xffffffffu, ps[j], 16);
            pq[j] += __shfl_xor_sync(0xffffffffu, pq[j], 16);
        }
        if (lane < 16) {
            #pragma unroll
            for (int j = 0; j < 4; ++j) {
                rbufS[wrp * 64 + c0 + j] = ps[j];
                rbufQ[wrp * 64 + c0 + j] = pq[j];
            }
        }
        __syncthreads();
        if (t < 64) {
            float s = 0.f, q2 = 0.f;
            #pragma unroll
            for (int w = 0; w < 8; ++w) { s += rbufS[w * 64 + t]; q2 += rbufQ[w * 64 + t]; }
            int off = (ct == 0) ? 0 : 320 + (ct - 1) * 64;
            atomicAdd(&g_sum[off + t], s);
            atomicAdd(&g_sqs[off + t], q2);
        }
        // loop-top __syncthreads() protects rbuf/Ws reuse
    }
}

__global__ void k_finalize(const float* __restrict__ g, const float* __restrict__ b,
                           int C, int off) {
    int c = blockIdx.x * blockDim.x + threadIdx.x;
    if (c >= C) return;
    float m  = g_sum[off + c] * (1.f / N_PTS);
    float v  = g_sqs[off + c] * (1.f / N_PTS) - m * m;
    float sc = g[c] * rsqrtf(v + EPS);
    g_scale[off + c] = sc;
    g_bias[off + c]  = b[c] - m * sc;
}

// ---------------- x1 = leakyrelu(BN1(y1)) ----------------
__global__ void k_bnact1() {
    int i = blockIdx.x * blockDim.x + threadIdx.x;   // float4 index
    if (i >= N_PTS * 16) return;
    int c = (i * 4) & 63;
    float4 v  = *(float4*)&g_y1[(size_t)i * 4];
    float4 s  = *(float4*)&g_scale[c];
    float4 bb = *(float4*)&g_bias[c];
    float4 o;
    o.x = lrelu(v.x * s.x + bb.x);
    o.y = lrelu(v.y * s.y + bb.y);
    o.z = lrelu(v.z * s.z + bb.z);
    o.w = lrelu(v.w * s.w + bb.w);
    *(float4*)&g_x1[(size_t)i * 4] = o;
}

// ---------------- KPConv gather + influence + fk accumulation ----------------
// 2 points per block, 256 threads
__global__ __launch_bounds__(256) void k_kpconv(const float* __restrict__ xyz,
                                                const int* __restrict__ nidx,
                                                const float* __restrict__ kp) {
    __shared__ float nxs[2][32][68];
    __shared__ float ws [2][32][16];
    __shared__ float rel[2][32][3];
    __shared__ int   idxs[2][32];
    int t = threadIdx.x;
    int p = t >> 7, tt = t & 127;
    int n = blockIdx.x * 2 + p;

    if (tt < 32) idxs[p][tt] = nidx[(size_t)n * 32 + tt];
    __syncthreads();

    {   // gather neighbor features (hits L2: x1 is 20.5 MB)
        int h = tt >> 2, q = tt & 3;
        const float* src = g_x1 + (size_t)idxs[p][h] * 64 + q * 16;
        #pragma unroll
        for (int j = 0; j < 4; ++j)
            *(float4*)&nxs[p][h][q * 16 + j * 4] = *(const float4*)&src[j * 4];
    }
    if (tt < 32) {
        int id = idxs[p][tt];
        rel[p][tt][0] = xyz[(size_t)id * 3 + 0] - xyz[(size_t)n * 3 + 0];
        rel[p][tt][1] = xyz[(size_t)id * 3 + 1] - xyz[(size_t)n * 3 + 1];
        rel[p][tt][2] = xyz[(size_t)id * 3 + 2] - xyz[(size_t)n * 3 + 2];
    }
    __syncthreads();

    for (int i = t; i < 2 * 32 * 16; i += 256) {
        int pp = i >> 9, hh = (i >> 4) & 31, k = i & 15;
        float wv = 0.f;
        if (k < 15) {
            float dx = rel[pp][hh][0] - kp[k * 3 + 0];
            float dy = rel[pp][hh][1] - kp[k * 3 + 1];
            float dz = rel[pp][hh][2] - kp[k * 3 + 2];
            wv = fmaxf(1.f - sqrtf(dx * dx + dy * dy + dz * dz) * INV_INFL, 0.f);
        }
        ws[pp][hh][k] = wv;
    }
    __syncthreads();

    int d = tt & 63, half = tt >> 6;
    int k0 = half * 8;
    float acc[8];
    #pragma unroll
    for (int j = 0; j < 8; ++j) acc[j] = 0.f;

    #pragma unroll 8
    for (int hh = 0; hh < 32; ++hh) {
        float nv = nxs[p][hh][d];
        float4 w0 = *(float4*)&ws[p][hh][k0];
        float4 w1 = *(float4*)&ws[p][hh][k0 + 4];
        acc[0] += w0.x * nv; acc[1] += w0.y * nv;
        acc[2] += w0.z * nv; acc[3] += w0.w * nv;
        acc[4] += w1.x * nv; acc[5] += w1.y * nv;
        acc[6] += w1.z * nv; acc[7] += w1.w * nv;
    }
    float* dst = g_fk + (size_t)n * 960 + d;
    #pragma unroll
    for (int j = 0; j < 8; ++j) {
        int k = k0 + j;
        if (k < 15) dst[k * 64] = acc[j];
    }
}

// ---------------- fused X = FK@Wflat[960,64]  then  y2 = X@W2[64,256] ----------------
// grid 625 x 256 thr. smem: FK[128][68] + Wf[64][68] + X[128][68] + rbuf 2x8x128
// BN2 column stats fused into phase-B epilogue
__global__ __launch_bounds__(256) void k_gemm2(const float* __restrict__ kpw,
                                               const float* __restrict__ W2) {
    extern __shared__ float sm[];
    float* FKs   = sm;                       // 128 x 68
    float* Wfs   = sm + 128 * 68;            // 64 x 68
    float* Xs    = sm + 128 * 68 + 64 * 68;  // 128 x 68
    float* W2s   = sm;                       // alias FKs/Wfs region in phase B (64 x 132)
    float* rbufS = sm + 128 * 68 + 64 * 68 + 128 * 68;   // 8 x 128
    float* rbufQ = rbufS + 8 * 128;                      // 8 x 128

    int t = threadIdx.x;
    int row0 = blockIdx.x * 128;
    int tr = t >> 4, tc = t & 15;
    int r0 = tr * 8, c0 = tc * 4;
    int lane = t & 31, wrp = t >> 5;

    float xacc[8][4];
    #pragma unroll
    for (int i = 0; i < 8; ++i)
        #pragma unroll
        for (int j = 0; j < 4; ++j) xacc[i][j] = 0.f;

    for (int k = 0; k < 15; ++k) {
        __syncthreads();
        for (int i = t; i < 128 * 16; i += 256) {
            int r = i >> 4, q = i & 15;
            *(float4*)&FKs[r * 68 + q * 4] =
                *(const float4*)&g_fk[(size_t)(row0 + r) * 960 + k * 64 + q * 4];
        }
        for (int i = t; i < 64 * 16; i += 256) {
            int r = i >> 4, q = i & 15;
            *(float4*)&Wfs[r * 68 + q * 4] =
                *(const float4*)&kpw[k * 4096 + r * 64 + q * 4];
        }
        __syncthreads();
        #pragma unroll 4
        for (int kk = 0; kk < 64; ++kk) {
            float4 b = *(float4*)&Wfs[kk * 68 + c0];
            #pragma unroll
            for (int i = 0; i < 8; ++i) {
                float a = FKs[(r0 + i) * 68 + kk];
                xacc[i][0] += a * b.x; xacc[i][1] += a * b.y;
                xacc[i][2] += a * b.z; xacc[i][3] += a * b.w;
            }
        }
    }
    __syncthreads();
    #pragma unroll
    for (int i = 0; i < 8; ++i) {
        float4 v = make_float4(xacc[i][0], xacc[i][1], xacc[i][2], xacc[i][3]);
        *(float4*)&Xs[(r0 + i) * 68 + c0] = v;
    }

    // phase B: y2 tile = Xs[128,64] @ W2[64, 256] in two 128-col halves
    int c2 = tc * 8;
    for (int ch = 0; ch < 2; ++ch) {
        __syncthreads();
        for (int i = t; i < 64 * 32; i += 256) {
            int r = i >> 5, q = i & 31;
            *(float4*)&W2s[r * 132 + q * 4] =
                *(const float4*)&W2[r * 256 + ch * 128 + q * 4];
        }
        __syncthreads();

        float acc2[8][8];
        #pragma unroll
        for (int i = 0; i < 8; ++i)
            #pragma unroll
            for (int j = 0; j < 8; ++j) acc2[i][j] = 0.f;

        #pragma unroll 2
        for (int kk = 0; kk < 64; ++kk) {
            float4 b0 = *(float4*)&W2s[kk * 132 + c2];
            float4 b1 = *(float4*)&W2s[kk * 132 + c2 + 4];
            #pragma unroll
            for (int i = 0; i < 8; ++i) {
                float a = Xs[(r0 + i) * 68 + kk];
                acc2[i][0] += a * b0.x; acc2[i][1] += a * b0.y;
                acc2[i][2] += a * b0.z; acc2[i][3] += a * b0.w;
                acc2[i][4] += a * b1.x; acc2[i][5] += a * b1.y;
                acc2[i][6] += a * b1.z; acc2[i][7] += a * b1.w;
            }
        }
        #pragma unroll
        for (int i = 0; i < 8; ++i) {
            size_t base = (size_t)(row0 + r0 + i) * 256 + ch * 128 + c2;
            *(float4*)&g_y2[base]     = make_float4(acc2[i][0], acc2[i][1], acc2[i][2], acc2[i][3]);
            *(float4*)&g_y2[base + 4] = make_float4(acc2[i][4], acc2[i][5], acc2[i][6], acc2[i][7]);
        }
        // ---- fused BN2 column stats ----
        float ps[8], pq[8];
        #pragma unroll
        for (int j = 0; j < 8; ++j) {
            float s = 0.f, q2 = 0.f;
            #pragma unroll
            for (int i = 0; i < 8; ++i) { float v = acc2[i][j]; s += v; q2 += v * v; }
            ps[j] = s; pq[j] = q2;
        }
        #pragma unroll
        for (int j = 0; j < 8; ++j) {
            ps[j] += __shfl_xor_sync(0xffffffffu, ps[j], 16);
            pq[j] += __shfl_xor_sync(0xffffffffu, pq[j], 16);
        }
        if (lane < 16) {
            #pragma unroll
            for (int j = 0; j < 8; ++j) {
                rbufS[wrp * 128 + c2 + j] = ps[j];
                rbufQ[wrp * 128 + c2 + j] = pq[j];
            }
        }
        __syncthreads();
        if (t < 128) {
            float s = 0.f, q2 = 0.f;
            #pragma unroll
            for (int w = 0; w < 8; ++w) { s += rbufS[w * 128 + t]; q2 += rbufQ[w * 128 + t]; }
            atomicAdd(&g_sum[64 + ch * 128 + t], s);
            atomicAdd(&g_sqs[64 + ch * 128 + t], q2);
        }
        // loop-top sync protects rbuf/W2s reuse
    }
}

// ---------------- out = leakyrelu(BN2(y2)) + BNsc(ysc) ----------------
__global__ void k_final(float* __restrict__ out) {
    int i = blockIdx.x * blockDim.x + threadIdx.x;   // float4 index
    if (i >= N_PTS * 64) return;
    int c = (i & 63) * 4;
    float4 y   = *(float4*)&g_y2 [(size_t)i * 4];
    float4 s2  = *(float4*)&g_scale[64 + c];
    float4 b2  = *(float4*)&g_bias [64 + c];
    float4 ys  = *(float4*)&g_ysc[(size_t)i * 4];
    float4 ssc = *(float4*)&g_scale[320 + c];
    float4 bsc = *(float4*)&g_bias [320 + c];
    float4 o;
    o.x = lrelu(y.x * s2.x + b2.x) + ys.x * ssc.x + bsc.x;
    o.y = lrelu(y.y * s2.y + b2.y) + ys.y * ssc.y + bsc.y;
    o.z = lrelu(y.z * s2.z + b2.z) + ys.z * ssc.z + bsc.z;
    o.w = lrelu(y.w * s2.w + b2.w) + ys.w * ssc.w + bsc.w;
    *(float4*)&out[(size_t)i * 4] = o;
}

// ---------------- launch ----------------
extern "C" void kernel_launch(void* const* d_in, const int* in_sizes, int n_in,
                              void* d_out, int out_size) {
    const float* feats = (const float*)d_in[0];
    const float* xyz   = (const float*)d_in[1];
    const int*   nidx  = (const int*)  d_in[3];
    const float* W1    = (const float*)d_in[4];
    const float* g1    = (const float*)d_in[5];
    const float* b1    = (const float*)d_in[6];
    const float* kp    = (const float*)d_in[7];
    const float* kpw   = (const float*)d_in[8];
    const float* W2    = (const float*)d_in[9];
    const float* g2    = (const float*)d_in[10];
    const float* b2    = (const float*)d_in[11];
    const float* Wsc   = (const float*)d_in[12];
    const float* gsc   = (const float*)d_in[13];
    const float* bsc   = (const float*)d_in[14];
    float* out = (float*)d_out;

    const int SM1 = (128 * 132 + 128 * 68 + 2 * 8 * 64) * 4;              // 106496 B
    const int SM2 = (128 * 68 * 2 + 64 * 68 + 2 * 8 * 128) * 4;           // 95232 B
    cudaFuncSetAttribute(k_gemm1sc, cudaFuncAttributeMaxDynamicSharedMemorySize, SM1);
    cudaFuncSetAttribute(k_gemm2,   cudaFuncAttributeMaxDynamicSharedMemorySize, SM2);

    k_zero<<<1, 576>>>();
    k_gemm1sc<<<625, 256, SM1>>>(feats, W1, Wsc);      // + BN1/BNsc stats fused
    k_finalize<<<1, 64>>>(g1, b1, 64, 0);
    k_finalize<<<1, 256>>>(gsc, bsc, 256, 320);
    k_bnact1<<<(N_PTS * 16 + 255) / 256, 256>>>();
    k_kpconv<<<N_PTS / 2, 256>>>(xyz, nidx, kp);
    k_gemm2<<<625, 256, SM2>>>(kpw, W2);               // + BN2 stats fused
    k_finalize<<<1, 256>>>(g2, b2, 256, 64);
    k_final<<<(N_PTS * 64 + 255) / 256, 256>>>(out);
}